// round 1
// baseline (speedup 1.0000x reference)
#include <cuda_runtime.h>
#include <math.h>

// ---------------------------------------------------------------------------
// NNConvNet: fused GNN forward.
//   x = node_attrs @ embed_W + embed_b                       (N,32)
//   ef = [vec, |vec|, edge_attr]                             (E,5)
//   3x: h1=relu(ef@W1+b1); h2=relu(h1@W2+b2);
//       w = relu(h2@W3+b3) reshaped (32,32) per edge (never materialized)
//       msg[e,k] = sum_h x[src,h]*w[h,k];  agg = segsum_dst(msg)+conv_b
//       x += relu(agg)
//   pooled = mean-by-batch(x); 4-layer selu MLP; gather by IDX -> (64,6,6)
// ---------------------------------------------------------------------------

#define NMAX 20000
#define EMAX 320000
#define BATCH 64

__device__ float g_x[NMAX * 32];
__device__ float g_agg[NMAX * 32];
__device__ float g_pooled[BATCH * 32];
__device__ float g_counts[BATCH];
__device__ unsigned int g_ticket[3];

__constant__ int c_IDX[36] = {
    0, 1, 2,  3,  4,  5,
    1, 6, 7,  8,  9,  10,
    2, 7, 11, 12, 13, 14,
    3, 8, 12, 15, 16, 17,
    4, 9, 13, 16, 18, 19,
    5, 10,14, 17, 19, 20};

// ---------------------------------------------------------------------------
// init: x = node_attrs*embed_W + embed_b ; zero agg / pooled / counts / tickets
// ---------------------------------------------------------------------------
__global__ void init_kernel(const float* __restrict__ node_attrs,
                            const float* __restrict__ embW,
                            const float* __restrict__ embB, int N) {
    int idx = blockIdx.x * blockDim.x + threadIdx.x;
    if (idx < N * 32) {
        int k = idx & 31;
        g_x[idx] = fmaf(node_attrs[idx >> 5], embW[k], embB[k]);
        g_agg[idx] = 0.f;
    }
    if (idx < BATCH * 32) g_pooled[idx] = 0.f;
    if (idx < BATCH) g_counts[idx] = 0.f;
    if (idx < 3) g_ticket[idx] = 0u;
}

// ---------------------------------------------------------------------------
// Edge kernel. lane = edge (32 edges per warp-task).
// W3 transposed in smem -> all weight reads are same-address broadcasts.
// Per-lane h2[32]/msg[32] live in registers (k,j loops fully unrolled);
// x[src] staged in padded smem (conflict-free: bank = (lane+h)&31).
// ---------------------------------------------------------------------------
#define EK_THREADS 512
#define EK_WARPS (EK_THREADS / 32)

#define SO_W3T 0                      // 32768 floats: W3T[col*32 + j]
#define SO_B3 32768                   // 1024
#define SO_W1 33792                   // 160
#define SO_B1 33952                   // 32
#define SO_W2T 33984                  // 1024: W2T[k*32 + j]
#define SO_B2 35008                   // 32
#define SO_XS 35040                   // EK_WARPS*32*33
#define SMEM_FLOATS (SO_XS + EK_WARPS * 32 * 33)

__global__ void __launch_bounds__(EK_THREADS)
edge_kernel(const float* __restrict__ positions,
            const float* __restrict__ shifts,
            const float* __restrict__ edge_attr,
            const int* __restrict__ eidx,
            const float* __restrict__ W1, const float* __restrict__ b1,
            const float* __restrict__ W2, const float* __restrict__ b2,
            const float* __restrict__ W3, const float* __restrict__ b3,
            int E, int layer) {
    extern __shared__ float sm[];

    // Stage weights (coalesced global reads; strided smem writes amortized
    // over the whole CTA lifetime).
    for (int i = threadIdx.x; i < 32 * 1024; i += blockDim.x) {
        int j = i >> 10, col = i & 1023;
        sm[SO_W3T + col * 32 + j] = W3[i];
    }
    for (int i = threadIdx.x; i < 1024; i += blockDim.x) {
        sm[SO_B3 + i] = b3[i];
        int j = i >> 5, k = i & 31;
        sm[SO_W2T + k * 32 + j] = W2[i];
    }
    for (int i = threadIdx.x; i < 160; i += blockDim.x) sm[SO_W1 + i] = W1[i];
    for (int i = threadIdx.x; i < 32; i += blockDim.x) {
        sm[SO_B1 + i] = b1[i];
        sm[SO_B2 + i] = b2[i];
    }
    __syncthreads();

    const int lane = threadIdx.x & 31;
    const int warp = threadIdx.x >> 5;
    float* xs = &sm[SO_XS + (warp * 32 + lane) * 33];

    const int* srcp = eidx;
    const int* dstp = eidx + E;
    const int ntasks = (E + 31) >> 5;

    for (;;) {
        int task;
        if (lane == 0) task = (int)atomicAdd(&g_ticket[layer], 1u);
        task = __shfl_sync(0xffffffffu, task, 0);
        if (task >= ntasks) break;

        int e = task * 32 + lane;
        bool valid = e < E;
        int si = 0, di = 0;
        float vx = 0.f, vy = 0.f, vz = 0.f, ea = 0.f;
        if (valid) {
            si = srcp[e];
            di = dstp[e];
            float px = positions[si * 3 + 0], py = positions[si * 3 + 1],
                  pz = positions[si * 3 + 2];
            float qx = positions[di * 3 + 0], qy = positions[di * 3 + 1],
                  qz = positions[di * 3 + 2];
            vx = qx - px + shifts[e * 3 + 0];
            vy = qy - py + shifts[e * 3 + 1];
            vz = qz - pz + shifts[e * 3 + 2];
            ea = edge_attr[e];
        }
        float len = sqrtf(vx * vx + vy * vy + vz * vz);

        // h1 = relu(ef @ W1 + b1)
        float h1[32];
#pragma unroll
        for (int k = 0; k < 32; k++) {
            float a = sm[SO_B1 + k];
            a = fmaf(vx, sm[SO_W1 + 0 * 32 + k], a);
            a = fmaf(vy, sm[SO_W1 + 1 * 32 + k], a);
            a = fmaf(vz, sm[SO_W1 + 2 * 32 + k], a);
            a = fmaf(len, sm[SO_W1 + 3 * 32 + k], a);
            a = fmaf(ea, sm[SO_W1 + 4 * 32 + k], a);
            h1[k] = fmaxf(a, 0.f);
        }

        // h2 = relu(h1 @ W2 + b2)
        float h2[32];
#pragma unroll
        for (int k = 0; k < 32; k++) {
            const float4* wp = (const float4*)&sm[SO_W2T + k * 32];
            float a0 = sm[SO_B2 + k], a1 = 0.f, a2 = 0.f, a3 = 0.f;
#pragma unroll
            for (int j = 0; j < 8; j++) {
                float4 w = wp[j];
                a0 = fmaf(h1[4 * j + 0], w.x, a0);
                a1 = fmaf(h1[4 * j + 1], w.y, a1);
                a2 = fmaf(h1[4 * j + 2], w.z, a2);
                a3 = fmaf(h1[4 * j + 3], w.w, a3);
            }
            h2[k] = fmaxf((a0 + a1) + (a2 + a3), 0.f);
        }

        // Stage x[src] per-lane into padded smem (dynamic h-index later).
        if (valid) {
            const float4* xr = (const float4*)(g_x + (size_t)si * 32);
#pragma unroll
            for (int t = 0; t < 8; t++) {
                float4 v = xr[t];
                xs[4 * t + 0] = v.x;
                xs[4 * t + 1] = v.y;
                xs[4 * t + 2] = v.z;
                xs[4 * t + 3] = v.w;
            }
        }

        // Fused: w[h,k] = relu(h2 . W3[:,h*32+k] + b3);  msg[k] += x_h * w[h,k]
        float msg[32];
#pragma unroll
        for (int k = 0; k < 32; k++) msg[k] = 0.f;

        for (int h = 0; h < 32; ++h) {
            float xh = xs[h];
            const float* wbase = &sm[SO_W3T + (h << 10)];
#pragma unroll
            for (int k = 0; k < 32; k++) {
                const float4* wp = (const float4*)(wbase + (k << 5));
                float a0 = sm[SO_B3 + (h << 5) + k], a1 = 0.f, a2 = 0.f,
                      a3 = 0.f;
#pragma unroll
                for (int j = 0; j < 8; j++) {
                    float4 w = wp[j];
                    a0 = fmaf(h2[4 * j + 0], w.x, a0);
                    a1 = fmaf(h2[4 * j + 1], w.y, a1);
                    a2 = fmaf(h2[4 * j + 2], w.z, a2);
                    a3 = fmaf(h2[4 * j + 3], w.w, a3);
                }
                float s = fmaxf((a0 + a1) + (a2 + a3), 0.f);
                msg[k] = fmaf(xh, s, msg[k]);
            }
        }

        if (valid) {
            float* ap = g_agg + (size_t)di * 32;
#pragma unroll
            for (int k = 0; k < 32; k++) atomicAdd(ap + k, msg[k]);
        }
    }
}

// ---------------------------------------------------------------------------
// Node update: x += relu(agg + conv_b); re-zero agg for next layer.
// ---------------------------------------------------------------------------
__global__ void node_kernel(const float* __restrict__ conv_b, int N) {
    int idx = blockIdx.x * blockDim.x + threadIdx.x;
    if (idx < N * 32) {
        float v = g_agg[idx] + conv_b[idx & 31];
        g_x[idx] += fmaxf(v, 0.f);
        g_agg[idx] = 0.f;
    }
}

// ---------------------------------------------------------------------------
// Pooling: segment sums into pooled / counts.
// ---------------------------------------------------------------------------
__global__ void pool_kernel(const int* __restrict__ batch_ids, int N) {
    int idx = blockIdx.x * blockDim.x + threadIdx.x;
    if (idx < N * 32) {
        int n = idx >> 5, k = idx & 31;
        int b = batch_ids[n];
        atomicAdd(&g_pooled[b * 32 + k], g_x[idx]);
        if (k == 0) atomicAdd(&g_counts[b], 1.f);
    }
}

// ---------------------------------------------------------------------------
// MLP head: one warp per batch row; selu; gather through IDX.
// ---------------------------------------------------------------------------
__device__ __forceinline__ float selu_f(float x) {
    const float alpha = 1.6732632423543772f;
    const float scale = 1.0507009873554805f;
    return x > 0.f ? scale * x : scale * alpha * expm1f(x);
}

__global__ void mlp_kernel(const float* __restrict__ W1,
                           const float* __restrict__ b1,
                           const float* __restrict__ W2,
                           const float* __restrict__ b2,
                           const float* __restrict__ W3,
                           const float* __restrict__ b3,
                           const float* __restrict__ W4,
                           const float* __restrict__ b4,
                           float* __restrict__ out) {
    __shared__ float sbuf[32][280];
    int warp = threadIdx.x >> 5, lane = threadIdx.x & 31;
    int b = blockIdx.x * 32 + warp;
    if (b >= BATCH) return;
    float* buf = sbuf[warp];

    float cnt = fmaxf(g_counts[b], 1.f);
    buf[lane] = g_pooled[b * 32 + lane] / cnt;
    __syncwarp();

    // 32 -> 128
#pragma unroll
    for (int r = 0; r < 4; r++) {
        int o = lane + 32 * r;
        float a = b1[o];
        for (int k = 0; k < 32; k++) a = fmaf(buf[k], W1[k * 128 + o], a);
        buf[32 + o] = selu_f(a);
    }
    __syncwarp();
    // 128 -> 64
#pragma unroll
    for (int r = 0; r < 2; r++) {
        int o = lane + 32 * r;
        float a = b2[o];
        for (int k = 0; k < 128; k++) a = fmaf(buf[32 + k], W2[k * 64 + o], a);
        buf[160 + o] = selu_f(a);
    }
    __syncwarp();
    // 64 -> 32
    {
        int o = lane;
        float a = b3[o];
        for (int k = 0; k < 64; k++) a = fmaf(buf[160 + k], W3[k * 32 + o], a);
        buf[224 + o] = selu_f(a);
    }
    __syncwarp();
    // 32 -> 21
    if (lane < 21) {
        float a = b4[lane];
        for (int k = 0; k < 32; k++) a = fmaf(buf[224 + k], W4[k * 21 + lane], a);
        buf[256 + lane] = a;
    }
    __syncwarp();
    // gather out[:, IDX]
    for (int r = lane; r < 36; r += 32) out[b * 36 + r] = buf[256 + c_IDX[r]];
}

// ---------------------------------------------------------------------------
// Launch
// ---------------------------------------------------------------------------
extern "C" void kernel_launch(void* const* d_in, const int* in_sizes, int n_in,
                              void* d_out, int out_size) {
    const float* node_attrs = (const float*)d_in[0];
    const float* positions = (const float*)d_in[1];
    const float* shifts = (const float*)d_in[2];
    const float* edge_attr = (const float*)d_in[3];
    const int* edge_index = (const int*)d_in[4];
    const int* batch_ids = (const int*)d_in[5];
    const float* embed_W = (const float*)d_in[6];
    const float* embed_b = (const float*)d_in[7];
    const float* e_W1 = (const float*)d_in[8];
    const float* e_b1 = (const float*)d_in[9];
    const float* e_W2 = (const float*)d_in[10];
    const float* e_b2 = (const float*)d_in[11];
    const float* e_W3 = (const float*)d_in[12];
    const float* e_b3 = (const float*)d_in[13];
    const float* conv_b = (const float*)d_in[14];
    const float* h_W1 = (const float*)d_in[15];
    const float* h_b1 = (const float*)d_in[16];
    const float* h_W2 = (const float*)d_in[17];
    const float* h_b2 = (const float*)d_in[18];
    const float* h_W3 = (const float*)d_in[19];
    const float* h_b3 = (const float*)d_in[20];
    const float* h_W4 = (const float*)d_in[21];
    const float* h_b4 = (const float*)d_in[22];

    int N = in_sizes[0];   // node_attrs: (N,1)
    int E = in_sizes[3];   // edge_attr:  (E,1)
    if (N > NMAX) N = NMAX;
    if (E > EMAX) E = EMAX;

    size_t smem_bytes = (size_t)SMEM_FLOATS * sizeof(float);
    cudaFuncSetAttribute(edge_kernel,
                         cudaFuncAttributeMaxDynamicSharedMemorySize,
                         (int)smem_bytes);

    int tot = N * 32;
    int blk = 256;
    init_kernel<<<(tot + blk - 1) / blk, blk>>>(node_attrs, embed_W, embed_b, N);

    for (int l = 0; l < 3; l++) {
        edge_kernel<<<148, EK_THREADS, smem_bytes>>>(
            positions, shifts, edge_attr, edge_index, e_W1 + l * 160,
            e_b1 + l * 32, e_W2 + l * 1024, e_b2 + l * 32, e_W3 + l * 32768,
            e_b3 + l * 1024, E, l);
        node_kernel<<<(tot + blk - 1) / blk, blk>>>(conv_b + l * 32, N);
    }

    pool_kernel<<<(tot + blk - 1) / blk, blk>>>(batch_ids, N);
    mlp_kernel<<<2, 1024>>>(h_W1, h_b1, h_W2, h_b2, h_W3, h_b3, h_W4, h_b4,
                            (float*)d_out);
}

// round 2
// speedup vs baseline: 1.4080x; 1.4080x over previous
#include <cuda_runtime.h>
#include <math.h>

// ---------------------------------------------------------------------------
// NNConvNet fused GNN forward — R1: lane=k edge kernel + f32x2.
// Phase 1 (lane=edge): ef -> h1 -> h2, stage h2/x_src/dst in smem.
// Phase 2 (lane=k):    fused w=relu(h2@W3+b3) and msg = sum_h x_h*w[h,k],
//                      4 edges register-blocked, fma.rn.f32x2 along j,
//                      W3 read coalesced (each lane its own k column).
// ---------------------------------------------------------------------------

#define NMAX 20000
#define EMAX 320000
#define BATCH 64

typedef unsigned long long ull;

__device__ float g_x[NMAX * 32];
__device__ float g_agg[NMAX * 32];
__device__ float g_pooled[BATCH * 32];
__device__ float g_counts[BATCH];
__device__ unsigned int g_ticket[3];

__constant__ int c_IDX[36] = {
    0, 1, 2,  3,  4,  5,
    1, 6, 7,  8,  9,  10,
    2, 7, 11, 12, 13, 14,
    3, 8, 12, 15, 16, 17,
    4, 9, 13, 16, 18, 19,
    5, 10,14, 17, 19, 20};

// ---------------------------------------------------------------------------
__global__ void init_kernel(const float* __restrict__ node_attrs,
                            const float* __restrict__ embW,
                            const float* __restrict__ embB, int N) {
    int idx = blockIdx.x * blockDim.x + threadIdx.x;
    if (idx < N * 32) {
        int k = idx & 31;
        g_x[idx] = fmaf(node_attrs[idx >> 5], embW[k], embB[k]);
        g_agg[idx] = 0.f;
    }
    if (idx < BATCH * 32) g_pooled[idx] = 0.f;
    if (idx < BATCH) g_counts[idx] = 0.f;
    if (idx < 3) g_ticket[idx] = 0u;
}

// ---------------------------------------------------------------------------
// Edge kernel, 256 threads (8 warps), 1 CTA/SM, persistent + ticket.
// ---------------------------------------------------------------------------
#define EK_THREADS 256
#define EK_WARPS 8

// smem layout (floats)
#define SO_W3 0                 // 32768: W3[j][col] natural layout
#define SO_B3 32768             // 1024
#define SO_W1 33792             // 160
#define SO_B1 33952             // 32
#define SO_W2T 33984            // 1024: W2T[k*32+j]
#define SO_B2 35008             // 32
#define SO_WS 35040             // per-warp: h2s(32*34) + xs(32*33) + dst(32)
#define WS_SIZE 2208
#define SMEM_FLOATS (SO_WS + EK_WARPS * WS_SIZE)

__device__ __forceinline__ ull pack2(float lo, float hi) {
    ull r;
    asm("mov.b64 %0, {%1, %2};" : "=l"(r) : "f"(lo), "f"(hi));
    return r;
}
__device__ __forceinline__ void unpack2(ull v, float& lo, float& hi) {
    asm("mov.b64 {%0, %1}, %2;" : "=f"(lo), "=f"(hi) : "l"(v));
}
__device__ __forceinline__ void fma2(ull& d, ull a, ull b) {
    asm("fma.rn.f32x2 %0, %1, %2, %0;" : "+l"(d) : "l"(a), "l"(b));
}
__device__ __forceinline__ void add2(ull& d, ull a, ull b) {
    asm("add.rn.f32x2 %0, %1, %2;" : "=l"(d) : "l"(a), "l"(b));
}

__global__ void __launch_bounds__(EK_THREADS, 1)
edge_kernel(const float* __restrict__ positions,
            const float* __restrict__ shifts,
            const float* __restrict__ edge_attr,
            const int* __restrict__ eidx,
            const float* __restrict__ W1, const float* __restrict__ b1,
            const float* __restrict__ W2, const float* __restrict__ b2,
            const float* __restrict__ W3, const float* __restrict__ b3,
            int E, int layer) {
    extern __shared__ float sm[];

    // Stage weights (W3 in NATURAL layout: row j, 1024 cols -> coalesced
    // lane=k reads later).
    for (int i = threadIdx.x; i < 32 * 1024; i += EK_THREADS)
        sm[SO_W3 + i] = W3[i];
    for (int i = threadIdx.x; i < 1024; i += EK_THREADS) {
        sm[SO_B3 + i] = b3[i];
        int j = i >> 5, k = i & 31;
        sm[SO_W2T + k * 32 + j] = W2[i];
    }
    if (threadIdx.x < 160) sm[SO_W1 + threadIdx.x] = W1[threadIdx.x];
    if (threadIdx.x < 32) {
        sm[SO_B1 + threadIdx.x] = b1[threadIdx.x];
        sm[SO_B2 + threadIdx.x] = b2[threadIdx.x];
    }
    __syncthreads();

    const int lane = threadIdx.x & 31;
    const int warp = threadIdx.x >> 5;
    float* h2s = sm + SO_WS + warp * WS_SIZE;   // [32][34]
    float* xs = h2s + 32 * 34;                  // [32][33]
    int* dsts = (int*)(xs + 32 * 33);           // [32]

    const int* srcp = eidx;
    const int* dstp = eidx + E;
    const int ntasks = (E + 31) >> 5;

    for (;;) {
        int task;
        if (lane == 0) task = (int)atomicAdd(&g_ticket[layer], 1u);
        task = __shfl_sync(0xffffffffu, task, 0);
        if (task >= ntasks) break;

        // ---------------- Phase 1: lane = edge ----------------
        int e = task * 32 + lane;
        bool valid = e < E;
        float vx = 0.f, vy = 0.f, vz = 0.f, ea = 0.f;
        int si = 0, di = 0;
        if (valid) {
            si = srcp[e];
            di = dstp[e];
            float px = positions[si * 3 + 0], py = positions[si * 3 + 1],
                  pz = positions[si * 3 + 2];
            float qx = positions[di * 3 + 0], qy = positions[di * 3 + 1],
                  qz = positions[di * 3 + 2];
            vx = qx - px + shifts[e * 3 + 0];
            vy = qy - py + shifts[e * 3 + 1];
            vz = qz - pz + shifts[e * 3 + 2];
            ea = edge_attr[e];
        }
        dsts[lane] = valid ? di : 0;
        float len = sqrtf(vx * vx + vy * vy + vz * vz);

        // h1
        float h1[32];
#pragma unroll
        for (int k = 0; k < 32; k++) {
            float a = sm[SO_B1 + k];
            a = fmaf(vx, sm[SO_W1 + 0 * 32 + k], a);
            a = fmaf(vy, sm[SO_W1 + 1 * 32 + k], a);
            a = fmaf(vz, sm[SO_W1 + 2 * 32 + k], a);
            a = fmaf(len, sm[SO_W1 + 3 * 32 + k], a);
            a = fmaf(ea, sm[SO_W1 + 4 * 32 + k], a);
            h1[k] = fmaxf(a, 0.f);
        }

        // h2 -> smem (zero for invalid edges so phase-2 msg contributions = 0)
#pragma unroll
        for (int k = 0; k < 32; k++) {
            const float4* wp = (const float4*)&sm[SO_W2T + k * 32];
            float a0 = sm[SO_B2 + k], a1 = 0.f, a2 = 0.f, a3 = 0.f;
#pragma unroll
            for (int j = 0; j < 8; j++) {
                float4 w = wp[j];
                a0 = fmaf(h1[4 * j + 0], w.x, a0);
                a1 = fmaf(h1[4 * j + 1], w.y, a1);
                a2 = fmaf(h1[4 * j + 2], w.z, a2);
                a3 = fmaf(h1[4 * j + 3], w.w, a3);
            }
            h2s[lane * 34 + k] = valid ? fmaxf((a0 + a1) + (a2 + a3), 0.f) : 0.f;
        }

        // x[src] -> smem (zero if invalid -> msg stays 0)
        if (valid) {
            const float4* xr = (const float4*)(g_x + (size_t)si * 32);
#pragma unroll
            for (int t = 0; t < 8; t++) {
                float4 v = xr[t];
                xs[lane * 33 + 4 * t + 0] = v.x;
                xs[lane * 33 + 4 * t + 1] = v.y;
                xs[lane * 33 + 4 * t + 2] = v.z;
                xs[lane * 33 + 4 * t + 3] = v.w;
            }
        } else {
#pragma unroll
            for (int t = 0; t < 32; t++) xs[lane * 33 + t] = 0.f;
        }
        __syncwarp();

        // ---------------- Phase 2: lane = k, 4 edges per pass ----------------
#pragma unroll 1
        for (int g = 0; g < 8; g++) {
            const int e0 = g * 4;
            // h2 pairs into registers (LDS.64 broadcast), 4 edges x 16 pairs
            ull h2p0[16], h2p1[16], h2p2[16], h2p3[16];
#pragma unroll
            for (int t = 0; t < 16; t++) {
                h2p0[t] = *(const ull*)(h2s + (e0 + 0) * 34 + 2 * t);
                h2p1[t] = *(const ull*)(h2s + (e0 + 1) * 34 + 2 * t);
                h2p2[t] = *(const ull*)(h2s + (e0 + 2) * 34 + 2 * t);
                h2p3[t] = *(const ull*)(h2s + (e0 + 3) * 34 + 2 * t);
            }
            float msg0 = 0.f, msg1 = 0.f, msg2 = 0.f, msg3 = 0.f;

#pragma unroll 1
            for (int h = 0; h < 32; h++) {
                float b3k = sm[SO_B3 + (h << 5) + lane];   // coalesced
                ull bpair = pack2(b3k, 0.f);

                // weights: coalesced LDS.32, lane owns column h*32+lane
                float w[32];
#pragma unroll
                for (int j = 0; j < 32; j++)
                    w[j] = sm[SO_W3 + (j << 10) + (h << 5) + lane];
                ull wp[16];
#pragma unroll
                for (int t = 0; t < 16; t++) wp[t] = pack2(w[2 * t], w[2 * t + 1]);

                float xh0 = xs[(e0 + 0) * 33 + h];
                float xh1 = xs[(e0 + 1) * 33 + h];
                float xh2 = xs[(e0 + 2) * 33 + h];
                float xh3 = xs[(e0 + 3) * 33 + h];

#define EDGE_BODY(HP, XH, MSG)                                        \
                {                                                     \
                    ull accA = bpair, accB = 0ull;                    \
                    _Pragma("unroll")                                 \
                    for (int t = 0; t < 8; t++) fma2(accA, HP[t], wp[t]); \
                    _Pragma("unroll")                                 \
                    for (int t = 8; t < 16; t++) fma2(accB, HP[t], wp[t]); \
                    ull accC; add2(accC, accA, accB);                 \
                    float lo, hi; unpack2(accC, lo, hi);              \
                    float s = fmaxf(lo + hi, 0.f);                    \
                    MSG = fmaf(XH, s, MSG);                           \
                }
                EDGE_BODY(h2p0, xh0, msg0)
                EDGE_BODY(h2p1, xh1, msg1)
                EDGE_BODY(h2p2, xh2, msg2)
                EDGE_BODY(h2p3, xh3, msg3)
#undef EDGE_BODY
            }

            // coalesced atomics: 32 lanes -> one node row
            atomicAdd(&g_agg[(size_t)dsts[e0 + 0] * 32 + lane], msg0);
            atomicAdd(&g_agg[(size_t)dsts[e0 + 1] * 32 + lane], msg1);
            atomicAdd(&g_agg[(size_t)dsts[e0 + 2] * 32 + lane], msg2);
            atomicAdd(&g_agg[(size_t)dsts[e0 + 3] * 32 + lane], msg3);
        }
        __syncwarp();
    }
}

// ---------------------------------------------------------------------------
__global__ void node_kernel(const float* __restrict__ conv_b, int N) {
    int idx = blockIdx.x * blockDim.x + threadIdx.x;
    if (idx < N * 32) {
        float v = g_agg[idx] + conv_b[idx & 31];
        g_x[idx] += fmaxf(v, 0.f);
        g_agg[idx] = 0.f;
    }
}

__global__ void pool_kernel(const int* __restrict__ batch_ids, int N) {
    int idx = blockIdx.x * blockDim.x + threadIdx.x;
    if (idx < N * 32) {
        int n = idx >> 5, k = idx & 31;
        int b = batch_ids[n];
        atomicAdd(&g_pooled[b * 32 + k], g_x[idx]);
        if (k == 0) atomicAdd(&g_counts[b], 1.f);
    }
}

__device__ __forceinline__ float selu_f(float x) {
    const float alpha = 1.6732632423543772f;
    const float scale = 1.0507009873554805f;
    return x > 0.f ? scale * x : scale * alpha * expm1f(x);
}

__global__ void mlp_kernel(const float* __restrict__ W1,
                           const float* __restrict__ b1,
                           const float* __restrict__ W2,
                           const float* __restrict__ b2,
                           const float* __restrict__ W3,
                           const float* __restrict__ b3,
                           const float* __restrict__ W4,
                           const float* __restrict__ b4,
                           float* __restrict__ out) {
    __shared__ float sbuf[32][280];
    int warp = threadIdx.x >> 5, lane = threadIdx.x & 31;
    int b = blockIdx.x * 32 + warp;
    if (b >= BATCH) return;
    float* buf = sbuf[warp];

    float cnt = fmaxf(g_counts[b], 1.f);
    buf[lane] = g_pooled[b * 32 + lane] / cnt;
    __syncwarp();

#pragma unroll
    for (int r = 0; r < 4; r++) {
        int o = lane + 32 * r;
        float a = b1[o];
        for (int k = 0; k < 32; k++) a = fmaf(buf[k], W1[k * 128 + o], a);
        buf[32 + o] = selu_f(a);
    }
    __syncwarp();
#pragma unroll
    for (int r = 0; r < 2; r++) {
        int o = lane + 32 * r;
        float a = b2[o];
        for (int k = 0; k < 128; k++) a = fmaf(buf[32 + k], W2[k * 64 + o], a);
        buf[160 + o] = selu_f(a);
    }
    __syncwarp();
    {
        int o = lane;
        float a = b3[o];
        for (int k = 0; k < 64; k++) a = fmaf(buf[160 + k], W3[k * 32 + o], a);
        buf[224 + o] = selu_f(a);
    }
    __syncwarp();
    if (lane < 21) {
        float a = b4[lane];
        for (int k = 0; k < 32; k++) a = fmaf(buf[224 + k], W4[k * 21 + lane], a);
        buf[256 + lane] = a;
    }
    __syncwarp();
    for (int r = lane; r < 36; r += 32) out[b * 36 + r] = buf[256 + c_IDX[r]];
}

// ---------------------------------------------------------------------------
extern "C" void kernel_launch(void* const* d_in, const int* in_sizes, int n_in,
                              void* d_out, int out_size) {
    const float* node_attrs = (const float*)d_in[0];
    const float* positions = (const float*)d_in[1];
    const float* shifts = (const float*)d_in[2];
    const float* edge_attr = (const float*)d_in[3];
    const int* edge_index = (const int*)d_in[4];
    const int* batch_ids = (const int*)d_in[5];
    const float* embed_W = (const float*)d_in[6];
    const float* embed_b = (const float*)d_in[7];
    const float* e_W1 = (const float*)d_in[8];
    const float* e_b1 = (const float*)d_in[9];
    const float* e_W2 = (const float*)d_in[10];
    const float* e_b2 = (const float*)d_in[11];
    const float* e_W3 = (const float*)d_in[12];
    const float* e_b3 = (const float*)d_in[13];
    const float* conv_b = (const float*)d_in[14];
    const float* h_W1 = (const float*)d_in[15];
    const float* h_b1 = (const float*)d_in[16];
    const float* h_W2 = (const float*)d_in[17];
    const float* h_b2 = (const float*)d_in[18];
    const float* h_W3 = (const float*)d_in[19];
    const float* h_b3 = (const float*)d_in[20];
    const float* h_W4 = (const float*)d_in[21];
    const float* h_b4 = (const float*)d_in[22];

    int N = in_sizes[0];
    int E = in_sizes[3];
    if (N > NMAX) N = NMAX;
    if (E > EMAX) E = EMAX;

    size_t smem_bytes = (size_t)SMEM_FLOATS * sizeof(float);
    cudaFuncSetAttribute(edge_kernel,
                         cudaFuncAttributeMaxDynamicSharedMemorySize,
                         (int)smem_bytes);

    int tot = N * 32;
    int blk = 256;
    init_kernel<<<(tot + blk - 1) / blk, blk>>>(node_attrs, embed_W, embed_b, N);

    for (int l = 0; l < 3; l++) {
        edge_kernel<<<148, EK_THREADS, smem_bytes>>>(
            positions, shifts, edge_attr, edge_index, e_W1 + l * 160,
            e_b1 + l * 32, e_W2 + l * 1024, e_b2 + l * 32, e_W3 + l * 32768,
            e_b3 + l * 1024, E, l);
        node_kernel<<<(tot + blk - 1) / blk, blk>>>(conv_b + l * 32, N);
    }

    pool_kernel<<<(tot + blk - 1) / blk, blk>>>(batch_ids, N);
    mlp_kernel<<<2, 1024>>>(h_W1, h_b1, h_W2, h_b2, h_W3, h_b3, h_W4, h_b4,
                            (float*)d_out);
}